// round 6
// baseline (speedup 1.0000x reference)
#include <cuda_runtime.h>
#include <cuda_bf16.h>
#include <cuda_fp16.h>
#include <math.h>
#include <stdint.h>

// ---------------- problem sizes ----------------
#define L_SEQ  2048
#define BATCH  2
#define DM     768
#define DI     1536
#define DS     16
#define M_ROWS (BATCH * L_SEQ)   // 4096
#define N_XZ   (2 * DI)          // 3072
#define N_COMB 1664              // 1536 + 32, padded to 13*128
#define CCH    32                // scan chunks
#define CL     64                // chunk length
#define SPL_OFF ((size_t)M_ROWS * N_COMB)   // split-K partial stride

typedef __nv_bfloat16 bf16;

// ---------------- scratch globals ----------------
__device__ __align__(128) float g_xz[M_ROWS * N_XZ];
__device__ __align__(128) float g_dx2[2 * M_ROWS * N_COMB];   // split-K partials
__device__ __align__(128) float g_xc[M_ROWS * DI];
__device__ __align__(128) float g_p [M_ROWS * DI];
__device__ __align__(128) float g_yp[M_ROWS * DI];

__device__ __align__(128) bf16 g_xh [M_ROWS * DM],  g_xl [M_ROWS * DM];
__device__ __align__(128) bf16 g_wih[N_XZ * DM],    g_wil[N_XZ * DM];
__device__ __align__(128) bf16 g_wch[N_COMB * DI],  g_wcl[N_COMB * DI];
__device__ __align__(128) bf16 g_xch[M_ROWS * DI],  g_xcl[M_ROWS * DI];
__device__ __align__(128) __half g_y16 [M_ROWS * DI];
__device__ __align__(128) __half g_wo16[DM * DI];

__device__ __align__(128) float g_cdec[BATCH * CCH * DS * DI];
__device__ __align__(128) float g_hend[BATCH * CCH * DS * DI];
__device__ __align__(128) float g_h0  [BATCH * CCH * DS * DI];

// ---------------- PTX helpers (plain sm_80+ PTX; NO tcgen05) --------
__device__ __forceinline__ uint32_t smem_u32(const void* p) {
    uint32_t a;
    asm("{ .reg .u64 t; cvta.to.shared.u64 t, %1; cvt.u32.u64 %0, t; }" : "=r"(a) : "l"(p));
    return a;
}
#define CP_ASYNC16(dst, src) \
    asm volatile("cp.async.cg.shared.global [%0], [%1], 16;" :: "r"(dst), "l"(src))
#define CP_COMMIT() asm volatile("cp.async.commit_group;")
#define CP_WAIT(n)  asm volatile("cp.async.wait_group %0;" :: "n"(n))
#define LDSM4(r, a) \
    asm volatile("ldmatrix.sync.aligned.m8n8.x4.shared.b16 {%0,%1,%2,%3}, [%4];" \
                 : "=r"((r)[0]), "=r"((r)[1]), "=r"((r)[2]), "=r"((r)[3]) : "r"(a))
#define MMA_BF16(c, a, b0, b1) \
    asm volatile("mma.sync.aligned.m16n8k16.row.col.f32.bf16.bf16.f32 " \
                 "{%0,%1,%2,%3}, {%4,%5,%6,%7}, {%8,%9}, {%0,%1,%2,%3};" \
                 : "+f"((c)[0]), "+f"((c)[1]), "+f"((c)[2]), "+f"((c)[3]) \
                 : "r"((a)[0]), "r"((a)[1]), "r"((a)[2]), "r"((a)[3]), \
                   "r"(b0), "r"(b1))
#define MMA_FP16(c, a, b0, b1) \
    asm volatile("mma.sync.aligned.m16n8k16.row.col.f32.f16.f16.f32 " \
                 "{%0,%1,%2,%3}, {%4,%5,%6,%7}, {%8,%9}, {%0,%1,%2,%3};" \
                 : "+f"((c)[0]), "+f"((c)[1]), "+f"((c)[2]), "+f"((c)[3]) \
                 : "r"((a)[0]), "r"((a)[1]), "r"((a)[2]), "r"((a)[3]), \
                   "r"(b0), "r"(b1))

// ---------------- HMMA bf16x3 GEMM: 256x128 tile, 8 warps of 64x64 ------
// BK=32; rows 80B (64B data + pad) conflict-free; 3-stage cp.async;
// 3 mma terms: hi*hi + hi*lo + lo*hi. 1 CTA/SM, 255-reg budget.
// Stage layout: Ah(20480) Al(20480) Bh(10240) Bl(10240) = 61440 B.
#define AT_B     20480
#define BT_B     10240
#define STAGE_B  61440
#define GSMEM    (3 * STAGE_B)    // 184320

__global__ __launch_bounds__(256, 1)
void gemm_mma(const bf16* __restrict__ Ah, const bf16* __restrict__ Al,
              const bf16* __restrict__ Bh, const bf16* __restrict__ Bl,
              float* __restrict__ C, int M, int N, int K, int klen) {
    extern __shared__ __align__(128) char smem[];
    const uint32_t sb = smem_u32(smem);
    const int tid  = threadIdx.x;
    const int lane = tid & 31;
    const int wid  = tid >> 5;
    const int wm   = wid & 3;          // 4 warps in M (64 rows each)
    const int wn   = wid >> 2;         // 2 warps in N (64 cols each)
    const int bm   = blockIdx.y * 256;
    const int bn   = blockIdx.x * 128;
    const int kstart = blockIdx.z * klen;
    C += (size_t)blockIdx.z * M * N;

    const bf16* sA_h = Ah + (size_t)bm * K + kstart;
    const bf16* sA_l = Al + (size_t)bm * K + kstart;
    const bf16* sB_h = Bh + (size_t)bn * K + kstart;
    const bf16* sB_l = Bl + (size_t)bn * K + kstart;

    // stage loader: 3072 chunks of 16B -> 12 per thread
    auto load_stage = [&](uint32_t stb, int k0) {
#pragma unroll
        for (int i = 0; i < 12; i++) {
            const int c = i * 256 + tid;
            if (c < 2048) {                 // A region (hi, lo)
                const int t = c >> 10, w = c & 1023, r = w >> 2, j = w & 3;
                const bf16* s = t ? sA_l : sA_h;
                CP_ASYNC16(stb + t * AT_B + r * 80 + j * 16,
                           s + (size_t)r * K + k0 + j * 8);
            } else {                        // B region (hi, lo)
                const int c2 = c - 2048;
                const int t = c2 >> 9, w = c2 & 511, r = w >> 2, j = w & 3;
                const bf16* s = t ? sB_l : sB_h;
                CP_ASYNC16(stb + 2 * AT_B + t * BT_B + r * 80 + j * 16,
                           s + (size_t)r * K + k0 + j * 8);
            }
        }
        CP_COMMIT();
    };

    float acc[4][8][4];
#pragma unroll
    for (int mt = 0; mt < 4; mt++)
#pragma unroll
        for (int nt = 0; nt < 8; nt++)
#pragma unroll
            for (int q = 0; q < 4; q++) acc[mt][nt][q] = 0.f;

    const uint32_t a_off = (uint32_t)((lane & 15) * 80 + (lane >> 4) * 16);
    const uint32_t b_off = (uint32_t)((((lane >> 4) << 3) + (lane & 7)) * 80 +
                                      ((lane >> 3) & 1) * 16);

    const int NC = klen >> 5;

    load_stage(sb, 0);
    load_stage(sb + STAGE_B, 32);

    for (int it = 0; it < NC; it++) {
        if (it + 2 < NC) {
            load_stage(sb + (uint32_t)((it + 2) % 3) * STAGE_B, (it + 2) << 5);
            CP_WAIT(2);
        } else if (it + 1 < NC) {
            CP_WAIT(1);
        } else {
            CP_WAIT(0);
        }
        __syncthreads();

        const uint32_t st  = sb + (uint32_t)(it % 3) * STAGE_B;
        const uint32_t aHb = st + wm * 64 * 80 + a_off;
        const uint32_t aLb = st + AT_B + wm * 64 * 80 + a_off;
        const uint32_t bHb = st + 2 * AT_B + wn * 64 * 80 + b_off;
        const uint32_t bLb = st + 2 * AT_B + BT_B + wn * 64 * 80 + b_off;

#pragma unroll
        for (int kk = 0; kk < 2; kk++) {
            const uint32_t ko = kk * 32;
            uint32_t ah[4][4], al[4][4];
#pragma unroll
            for (int mt = 0; mt < 4; mt++) {
                LDSM4(ah[mt], aHb + mt * 16 * 80 + ko);
                LDSM4(al[mt], aLb + mt * 16 * 80 + ko);
            }
#pragma unroll
            for (int half = 0; half < 2; half++) {
                uint32_t bh[2][4], bl[2][4];
#pragma unroll
                for (int u = 0; u < 2; u++) {
                    const int bt = half * 2 + u;
                    LDSM4(bh[u], bHb + bt * 16 * 80 + ko);
                    LDSM4(bl[u], bLb + bt * 16 * 80 + ko);
                }
                // term-major: max reuse distance on each accumulator
#pragma unroll
                for (int mt = 0; mt < 4; mt++)
#pragma unroll
                    for (int v = 0; v < 4; v++) {
                        const int nt = half * 4 + v;
                        const int u = v >> 1, hh = (v & 1) << 1;
                        MMA_BF16(acc[mt][nt], ah[mt], bh[u][hh], bh[u][hh + 1]);
                    }
#pragma unroll
                for (int mt = 0; mt < 4; mt++)
#pragma unroll
                    for (int v = 0; v < 4; v++) {
                        const int nt = half * 4 + v;
                        const int u = v >> 1, hh = (v & 1) << 1;
                        MMA_BF16(acc[mt][nt], ah[mt], bl[u][hh], bl[u][hh + 1]);
                    }
#pragma unroll
                for (int mt = 0; mt < 4; mt++)
#pragma unroll
                    for (int v = 0; v < 4; v++) {
                        const int nt = half * 4 + v;
                        const int u = v >> 1, hh = (v & 1) << 1;
                        MMA_BF16(acc[mt][nt], al[mt], bh[u][hh], bh[u][hh + 1]);
                    }
            }
        }
        __syncthreads();
    }

    const int r0 = bm + wm * 64 + (lane >> 2);
    const int c0 = bn + wn * 64 + (lane & 3) * 2;
#pragma unroll
    for (int mt = 0; mt < 4; mt++)
#pragma unroll
        for (int nt = 0; nt < 8; nt++) {
            float* p0 = C + (size_t)(r0 + mt * 16) * N + c0 + nt * 8;
            *(float2*)p0                   = make_float2(acc[mt][nt][0], acc[mt][nt][1]);
            *(float2*)(p0 + (size_t)8 * N) = make_float2(acc[mt][nt][2], acc[mt][nt][3]);
        }
}

// ---------------- fp16 single-term GEMM (final projection) ----------------
#define T3_TILE_A 5120            // 64 * 80
#define T3_STAGE  15360           // A(5120) + B(10240)
#define T3_SMEM   (2 * T3_STAGE)  // 30720

__global__ __launch_bounds__(256, 3)
void gemm_fp16(const __half* __restrict__ A, const __half* __restrict__ B,
               float* __restrict__ C, int M, int N, int K) {
    extern __shared__ __align__(128) char smem[];
    const uint32_t sb = smem_u32(smem);
    const int tid  = threadIdx.x;
    const int lane = tid & 31;
    const int wid  = tid >> 5;
    const int wm   = wid & 1;          // 2 warps in M
    const int wn   = wid >> 1;         // 4 warps in N
    const int bm   = blockIdx.y * 64;
    const int bn   = blockIdx.x * 128;

    const __half* srcA = A + (size_t)bm * K;
    const __half* srcB = B + (size_t)bn * K;

    float acc[2][4][4];
#pragma unroll
    for (int mt = 0; mt < 2; mt++)
#pragma unroll
        for (int nt = 0; nt < 4; nt++)
#pragma unroll
            for (int q = 0; q < 4; q++) acc[mt][nt][q] = 0.f;

    const uint32_t a_off = (uint32_t)((lane & 15) * 80 + (lane >> 4) * 16);
    const uint32_t b_off = (uint32_t)((((lane >> 4) << 3) + (lane & 7)) * 80 +
                                      ((lane >> 3) & 1) * 16);

    const int NC = K >> 5;

    auto load_stage = [&](uint32_t stb, int k0) {
#pragma unroll
        for (int i = 0; i < 3; i++) {
            int c = i * 256 + tid;
            if (c < 256) {
                int r = c >> 2, j = c & 3;
                CP_ASYNC16(stb + r * 80 + j * 16,
                           srcA + (size_t)r * K + k0 + j * 8);
            } else {
                int c2 = c - 256;
                int r = c2 >> 2, j = c2 & 3;
                CP_ASYNC16(stb + T3_TILE_A + r * 80 + j * 16,
                           srcB + (size_t)r * K + k0 + j * 8);
            }
        }
        CP_COMMIT();
    };

    load_stage(sb, 0);

    for (int it = 0; it < NC; it++) {
        if (it + 1 < NC) {
            load_stage(sb + ((it + 1) & 1) * T3_STAGE, (it + 1) << 5);
            CP_WAIT(1);
        } else {
            CP_WAIT(0);
        }
        __syncthreads();

        const uint32_t st = sb + (it & 1) * T3_STAGE;
        const uint32_t aB = st + wm * 32 * 80 + a_off;
        const uint32_t bB = st + T3_TILE_A + wn * 32 * 80 + b_off;

#pragma unroll
        for (int kk = 0; kk < 2; kk++) {
            const uint32_t ko = kk * 32;
            uint32_t ah[2][4], bb[2][4];
#pragma unroll
            for (int mt = 0; mt < 2; mt++)
                LDSM4(ah[mt], aB + mt * 16 * 80 + ko);
#pragma unroll
            for (int bt = 0; bt < 2; bt++)
                LDSM4(bb[bt], bB + bt * 16 * 80 + ko);
#pragma unroll
            for (int mt = 0; mt < 2; mt++)
#pragma unroll
                for (int nt = 0; nt < 4; nt++) {
                    const int bt = nt >> 1, hh = (nt & 1) << 1;
                    MMA_FP16(acc[mt][nt], ah[mt], bb[bt][hh], bb[bt][hh + 1]);
                }
        }
        __syncthreads();
    }

    const int r0 = bm + wm * 32 + (lane >> 2);
    const int c0 = bn + wn * 32 + (lane & 3) * 2;
#pragma unroll
    for (int mt = 0; mt < 2; mt++)
#pragma unroll
        for (int nt = 0; nt < 4; nt++) {
            float* p0 = C + (size_t)(r0 + mt * 16) * N + c0 + nt * 8;
            *(float2*)p0                   = make_float2(acc[mt][nt][0], acc[mt][nt][1]);
            *(float2*)(p0 + (size_t)8 * N) = make_float2(acc[mt][nt][2], acc[mt][nt][3]);
        }
}

// ---------------- fp32 -> bf16 hi/lo split ----------------
__device__ __forceinline__ void split_bf16(float v, bf16& h, bf16& l) {
    h = __float2bfloat16_rn(v);
    l = __float2bfloat16_rn(v - __bfloat162float(h));
}

// fused prep: split x, W_in; W_out->fp16; pack+split [W_dt;W_x;0]
#define N_JOB0 (M_ROWS * DM)
#define N_JOB1 (N_XZ * DM)
#define N_JOB2 (DM * DI)
#define N_JOB3 (N_COMB * DI)
#define N_PREP (N_JOB0 + N_JOB1 + N_JOB2 + N_JOB3)
__global__ void prep_k(const float* __restrict__ x, const float* __restrict__ Win,
                       const float* __restrict__ Wout,
                       const float* __restrict__ Wdt, const float* __restrict__ Wx) {
    int idx = blockIdx.x * 256 + threadIdx.x;
    if (idx < N_JOB0) {
        split_bf16(x[idx], g_xh[idx], g_xl[idx]);
        return;
    }
    idx -= N_JOB0;
    if (idx < N_JOB1) {
        split_bf16(Win[idx], g_wih[idx], g_wil[idx]);
        return;
    }
    idx -= N_JOB1;
    if (idx < N_JOB2) {
        g_wo16[idx] = __float2half_rn(Wout[idx]);
        return;
    }
    idx -= N_JOB2;
    if (idx < N_JOB3) {
        int row = idx / DI, col = idx - row * DI;
        float v = 0.f;
        if (row < DI)           v = Wdt[idx];
        else if (row < DI + 32) v = Wx[(row - DI) * DI + col];
        split_bf16(v, g_wch[idx], g_wcl[idx]);
    }
}

// ---------------- conv + SiLU (fp32 + bf16 split outputs) ----------------
__global__ void conv_silu_k(const float* __restrict__ Wc) {
    int idx = blockIdx.x * 256 + threadIdx.x;
    if (idx >= M_ROWS * DI) return;
    int d = idx % DI, m = idx / DI, l = m & (L_SEQ - 1);
    float w0 = Wc[d*4+0], w1 = Wc[d*4+1], w2 = Wc[d*4+2], w3 = Wc[d*4+3];
    float s = g_xz[(size_t)m * N_XZ + d] * w3;
    if (l >= 1) s = fmaf(g_xz[(size_t)(m-1) * N_XZ + d], w2, s);
    if (l >= 2) s = fmaf(g_xz[(size_t)(m-2) * N_XZ + d], w1, s);
    if (l >= 3) s = fmaf(g_xz[(size_t)(m-3) * N_XZ + d], w0, s);
    float v = __fdividef(s, 1.f + __expf(-s));
    g_xc[idx] = v;
    split_bf16(v, g_xch[idx], g_xcl[idx]);
}

// ---------------- scan helpers ----------------
__device__ __forceinline__ void pow16(float p, float* pw) {
    pw[0]=p;          pw[1]=p*p;        pw[2]=pw[1]*p;     pw[3]=pw[1]*pw[1];
    pw[4]=pw[3]*p;    pw[5]=pw[3]*pw[1];pw[6]=pw[3]*pw[2]; pw[7]=pw[3]*pw[3];
    pw[8]=pw[7]*p;    pw[9]=pw[7]*pw[1];pw[10]=pw[7]*pw[2];pw[11]=pw[7]*pw[3];
    pw[12]=pw[7]*pw[4];pw[13]=pw[7]*pw[5];pw[14]=pw[7]*pw[6];pw[15]=pw[7]*pw[7];
}
__device__ __forceinline__ bool geo_check(const float* Alog, float* A) {
#pragma unroll
    for (int s = 0; s < DS; s++) A[s] = -__expf(Alog[s]);
    bool geo = true;
#pragma unroll
    for (int s = 0; s < DS; s++)
        geo = geo && (fabsf(A[s] - (float)(s + 1) * A[0]) <= 1e-5f * fabsf(A[s]));
    return geo;
}
__device__ __forceinline__ float softplus_f(float x) {
    return (x > 20.f) ? x : log1pf(__expf(x));
}
__device__ __forceinline__ float dx_sum(size_t idx) {
    return g_dx2[idx] + g_dx2[SPL_OFF + idx];
}

// ---------------- scan phase A: local scans ----------------
__global__ __launch_bounds__(128)
void scan_a(const float* __restrict__ Alog, const float* __restrict__ bdt) {
    __shared__ float sBC[CL * 32];
    const int d = blockIdx.x * 128 + threadIdx.x;
    const int c = blockIdx.y, b = blockIdx.z;
    const int m0 = b * L_SEQ + c * CL;
    for (int e = threadIdx.x; e < CL * 32; e += 128) {
        int l = e >> 5, q = e & 31;
        sBC[e] = dx_sum((size_t)(m0 + l) * N_COMB + DI + q);
    }
    __syncthreads();

    float A[DS];
    const bool geo = geo_check(Alog, A);
    const float bd = bdt[d];
    float h[DS];
#pragma unroll
    for (int s = 0; s < DS; s++) h[s] = 0.f;
    const size_t base = ((size_t)(b * CCH + c) * DS) * DI + d;

    if (geo) {
        const float A0 = A[0];
        float pp = 1.f;
        for (int l = 0; l < CL; l++) {
            const size_t m = m0 + l;
            float dt = softplus_f(dx_sum(m * N_COMB + d) + bd);
            float p = __expf(A0 * dt);
            g_p[m * DI + d] = p;
            pp *= p;
            float pw[DS]; pow16(p, pw);
            float y0=0.f, y1=0.f, y2=0.f, y3=0.f;
#pragma unroll
            for (int s = 0; s < DS; s++) {
                h[s] = fmaf(pw[s], h[s], dt * sBC[l * 32 + s]);
                float t = h[s] * sBC[l * 32 + 16 + s];
                if ((s&3)==0) y0+=t; else if ((s&3)==1) y1+=t;
                else if ((s&3)==2) y2+=t; else y3+=t;
            }
            g_yp[m * DI + d] = (y0 + y1) + (y2 + y3);
        }
        float dw[DS]; pow16(pp, dw);
#pragma unroll
        for (int s = 0; s < DS; s++) {
            g_cdec[base + (size_t)s * DI] = dw[s];
            g_hend[base + (size_t)s * DI] = h[s];
        }
    } else {
        float dec[DS];
#pragma unroll
        for (int s = 0; s < DS; s++) dec[s] = 1.f;
        for (int l = 0; l < CL; l++) {
            const size_t m = m0 + l;
            float dt = softplus_f(dx_sum(m * N_COMB + d) + bd);
            float y0=0.f, y1=0.f, y2=0.f, y3=0.f;
#pragma unroll
            for (int s = 0; s < DS; s++) {
                float dA = __expf(A[s] * dt);
                dec[s] *= dA;
                h[s] = fmaf(dA, h[s], dt * sBC[l * 32 + s]);
                float t = h[s] * sBC[l * 32 + 16 + s];
                if ((s&3)==0) y0+=t; else if ((s&3)==1) y1+=t;
                else if ((s&3)==2) y2+=t; else y3+=t;
            }
            g_yp[m * DI + d] = (y0 + y1) + (y2 + y3);
        }
#pragma unroll
        for (int s = 0; s < DS; s++) {
            g_cdec[base + (size_t)s * DI] = dec[s];
            g_hend[base + (size_t)s * DI] = h[s];
        }
    }
}

// ---------------- scan phase B: chunk combine ----------------
__global__ __launch_bounds__(128)
void scan_b() {
    const int d = blockIdx.x * 128 + threadIdx.x;
    const int b = blockIdx.y;
    float H[DS];
#pragma unroll
    for (int s = 0; s < DS; s++) H[s] = 0.f;
    for (int c = 0; c < CCH; c++) {
        const size_t base = ((size_t)(b * CCH + c) * DS) * DI + d;
#pragma unroll
        for (int s = 0; s < DS; s++) {
            g_h0[base + (size_t)s * DI] = H[s];
            H[s] = fmaf(g_cdec[base + (size_t)s * DI], H[s],
                        g_hend[base + (size_t)s * DI]);
        }
    }
}

// ---------------- scan phase C: correction + gate + fp16 out ----------------
__global__ __launch_bounds__(128)
void scan_c(const float* __restrict__ Alog, const float* __restrict__ Dp,
            const float* __restrict__ bdt) {
    __shared__ float sC[CL * 16];
    const int d = blockIdx.x * 128 + threadIdx.x;
    const int c = blockIdx.y, b = blockIdx.z;
    const int m0 = b * L_SEQ + c * CL;
    for (int e = threadIdx.x; e < CL * 16; e += 128) {
        int l = e >> 4, q = e & 15;
        sC[e] = dx_sum((size_t)(m0 + l) * N_COMB + DI + 16 + q);
    }
    __syncthreads();

    float A[DS];
    const bool geo = geo_check(Alog, A);
    const float Dd = Dp[d];
    const float bd = bdt[d];
    float H0[DS];
    const size_t base = ((size_t)(b * CCH + c) * DS) * DI + d;
#pragma unroll
    for (int s = 0; s < DS; s++) H0[s] = g_h0[base + (size_t)s * DI];

    if (geo) {
        float run = 1.f;
        for (int l = 0; l < CL; l++) {
            const size_t m = m0 + l;
            run *= g_p[m * DI + d];
            float rw[DS]; pow16(run, rw);
            float corr = 0.f;
#pragma unroll
            for (int s = 0; s < DS; s++)
                corr = fmaf(rw[s] * H0[s], sC[l * 16 + s], corr);
            float y = g_yp[m * DI + d] + corr;
            float z = g_xz[m * N_XZ + DI + d];
            float o = (y + Dd * g_xc[m * DI + d]) *
                      __fdividef(z, 1.f + __expf(-z));
            g_y16[m * DI + d] = __float2half_rn(o);
        }
    } else {
        float run[DS];
#pragma unroll
        for (int s = 0; s < DS; s++) run[s] = 1.f;
        for (int l = 0; l < CL; l++) {
            const size_t m = m0 + l;
            float dt = softplus_f(dx_sum(m * N_COMB + d) + bd);
            float corr = 0.f;
#pragma unroll
            for (int s = 0; s < DS; s++) {
                run[s] *= __expf(A[s] * dt);
                corr = fmaf(run[s] * H0[s], sC[l * 16 + s], corr);
            }
            float y = g_yp[m * DI + d] + corr;
            float z = g_xz[m * N_XZ + DI + d];
            float o = (y + Dd * g_xc[m * DI + d]) *
                      __fdividef(z, 1.f + __expf(-z));
            g_y16[m * DI + d] = __float2half_rn(o);
        }
    }
}

// ---------------- launch ----------------
extern "C" void kernel_launch(void* const* d_in, const int* in_sizes, int n_in,
                              void* d_out, int out_size) {
    const float* x      = (const float*)d_in[0];
    const float* W_in   = (const float*)d_in[1];
    const float* W_conv = (const float*)d_in[2];
    const float* W_x    = (const float*)d_in[3];
    const float* W_dt   = (const float*)d_in[4];
    const float* b_dt   = (const float*)d_in[5];
    const float* A_log  = (const float*)d_in[6];
    const float* Dp     = (const float*)d_in[7];
    const float* W_out  = (const float*)d_in[8];
    float* out = (float*)d_out;

    cudaFuncSetAttribute(gemm_mma, cudaFuncAttributeMaxDynamicSharedMemorySize,
                         GSMEM);
    cudaFuncSetAttribute(gemm_fp16, cudaFuncAttributeMaxDynamicSharedMemorySize,
                         T3_SMEM);

    float *xz, *dx2;
    bf16 *xh, *xl, *wih, *wil, *wch, *wcl, *xch, *xcl;
    __half *y16, *wo16;
    cudaGetSymbolAddress((void**)&xz,   g_xz);
    cudaGetSymbolAddress((void**)&dx2,  g_dx2);
    cudaGetSymbolAddress((void**)&xh,   g_xh);  cudaGetSymbolAddress((void**)&xl,   g_xl);
    cudaGetSymbolAddress((void**)&wih,  g_wih); cudaGetSymbolAddress((void**)&wil,  g_wil);
    cudaGetSymbolAddress((void**)&wch,  g_wch); cudaGetSymbolAddress((void**)&wcl,  g_wcl);
    cudaGetSymbolAddress((void**)&xch,  g_xch); cudaGetSymbolAddress((void**)&xcl,  g_xcl);
    cudaGetSymbolAddress((void**)&y16,  g_y16); cudaGetSymbolAddress((void**)&wo16, g_wo16);

    // fused prep: splits + weight pack + W_out fp16
    prep_k<<<(N_PREP + 255)/256, 256>>>(x, W_in, W_out, W_dt, W_x);

    // xz = x @ W_in^T   (256x128 tiles)
    gemm_mma<<<dim3(N_XZ/128, M_ROWS/256, 1), 256, GSMEM>>>(
        xh, xl, wih, wil, xz, M_ROWS, N_XZ, DM, DM);
    // xc = silu(conv(xz[:, :di]))
    conv_silu_k<<<(M_ROWS*DI + 255)/256, 256>>>(W_conv);
    // dx = xc @ [W_dt;W_x;0]^T  (split-K 2, partials summed in scan kernels)
    gemm_mma<<<dim3(N_COMB/128, M_ROWS/256, 2), 256, GSMEM>>>(
        xch, xcl, wch, wcl, dx2, M_ROWS, N_COMB, DI, DI/2);
    // chunked selective scan
    scan_a<<<dim3(DI/128, CCH, BATCH), 128>>>(A_log, b_dt);
    scan_b<<<dim3(DI/128, BATCH), 128>>>();
    scan_c<<<dim3(DI/128, CCH, BATCH), 128>>>(A_log, Dp, b_dt);
    // out = y @ W_out^T  (fp16 single-term)
    gemm_fp16<<<dim3(DM/128, M_ROWS/64), 256, T3_SMEM>>>(
        y16, wo16, out, M_ROWS, DM, DI);
}

// round 7
// speedup vs baseline: 1.2876x; 1.2876x over previous
#include <cuda_runtime.h>
#include <cuda_bf16.h>
#include <cuda_fp16.h>
#include <math.h>
#include <stdint.h>

// ---------------- problem sizes ----------------
#define L_SEQ  2048
#define BATCH  2
#define DM     768
#define DI     1536
#define DS     16
#define M_ROWS (BATCH * L_SEQ)   // 4096
#define N_XZ   (2 * DI)          // 3072
#define N_COMB 1664              // 1536 + 32, padded to 13*128
#define CCH    32                // scan chunks
#define CL     64                // chunk length

typedef __nv_bfloat16 bf16;

// ---------------- scratch globals ----------------
__device__ __align__(128) float g_xz[M_ROWS * N_XZ];
__device__ __align__(128) float g_dx[M_ROWS * N_COMB];
__device__ __align__(128) float g_xc[M_ROWS * DI];
__device__ __align__(128) float g_p [M_ROWS * DI];
__device__ __align__(128) float g_yp[M_ROWS * DI];

__device__ __align__(128) __half g_xh [M_ROWS * DM],  g_xl [M_ROWS * DM];
__device__ __align__(128) __half g_wi16[N_XZ * DM];
__device__ __align__(128) __half g_wc16[N_COMB * DI];
__device__ __align__(128) __half g_xch[M_ROWS * DI],  g_xcl[M_ROWS * DI];
__device__ __align__(128) __half g_y16 [M_ROWS * DI];
__device__ __align__(128) __half g_wo16[DM * DI];

__device__ __align__(128) float g_cdec[BATCH * CCH * DS * DI];
__device__ __align__(128) float g_hend[BATCH * CCH * DS * DI];
__device__ __align__(128) float g_h0  [BATCH * CCH * DS * DI];

// ---------------- PTX helpers (plain sm_80+ PTX; NO tcgen05) --------
__device__ __forceinline__ uint32_t smem_u32(const void* p) {
    uint32_t a;
    asm("{ .reg .u64 t; cvta.to.shared.u64 t, %1; cvt.u32.u64 %0, t; }" : "=r"(a) : "l"(p));
    return a;
}
#define CP_ASYNC16(dst, src) \
    asm volatile("cp.async.cg.shared.global [%0], [%1], 16;" :: "r"(dst), "l"(src))
#define CP_COMMIT() asm volatile("cp.async.commit_group;")
#define CP_WAIT(n)  asm volatile("cp.async.wait_group %0;" :: "n"(n))
#define LDSM4(r, a) \
    asm volatile("ldmatrix.sync.aligned.m8n8.x4.shared.b16 {%0,%1,%2,%3}, [%4];" \
                 : "=r"((r)[0]), "=r"((r)[1]), "=r"((r)[2]), "=r"((r)[3]) : "r"(a))
#define MMA_FP16(c, a, b0, b1) \
    asm volatile("mma.sync.aligned.m16n8k16.row.col.f32.f16.f16.f32 " \
                 "{%0,%1,%2,%3}, {%4,%5,%6,%7}, {%8,%9}, {%0,%1,%2,%3};" \
                 : "+f"((c)[0]), "+f"((c)[1]), "+f"((c)[2]), "+f"((c)[3]) \
                 : "r"((a)[0]), "r"((a)[1]), "r"((a)[2]), "r"((a)[3]), \
                   "r"(b0), "r"(b1))

// ---------------- fp16 2-term GEMM: C[M,N] = (Ah+Al) B^T ----------------
// 128x128 tile, BK=32; rows 80B (64B data + pad); 2-stage cp.async;
// 2 mma terms: Ah*B + Al*B. 2 CTAs/SM via 128-reg cap.
#define F2_TILE  10240            // 128 rows * 80 bytes
#define F2_STAGE 30720            // Ah, Al, B
#define F2_SMEM  (2 * F2_STAGE)   // 61440

__global__ __launch_bounds__(256, 2)
void gemm_f16x2(const __half* __restrict__ Ah, const __half* __restrict__ Al,
                const __half* __restrict__ B, float* __restrict__ C,
                int M, int N, int K) {
    extern __shared__ __align__(128) char smem[];
    const uint32_t sb = smem_u32(smem);
    const int tid  = threadIdx.x;
    const int lane = tid & 31;
    const int wid  = tid >> 5;
    const int wm   = wid & 3;          // 4 warps in M (32 rows each)
    const int wn   = wid >> 2;         // 2 warps in N (64 cols each)
    const int bm   = blockIdx.y * 128;
    const int bn   = blockIdx.x * 128;

    const __half* srcs[3] = { Ah + (size_t)bm * K, Al + (size_t)bm * K,
                              B + (size_t)bn * K };

    // stage loader: 1536 chunks of 16B -> 6 per thread
    auto load_stage = [&](uint32_t stb, int k0) {
#pragma unroll
        for (int i = 0; i < 6; i++) {
            const int c = i * 256 + tid;
            const int t = c >> 9, w = c & 511, r = w >> 2, j = w & 3;
            CP_ASYNC16(stb + t * F2_TILE + r * 80 + j * 16,
                       srcs[t] + (size_t)r * K + k0 + j * 8);
        }
        CP_COMMIT();
    };

    float acc[2][8][4];
#pragma unroll
    for (int mt = 0; mt < 2; mt++)
#pragma unroll
        for (int nt = 0; nt < 8; nt++)
#pragma unroll
            for (int q = 0; q < 4; q++) acc[mt][nt][q] = 0.f;

    const uint32_t a_off = (uint32_t)((lane & 15) * 80 + (lane >> 4) * 16);
    const uint32_t b_off = (uint32_t)((((lane >> 4) << 3) + (lane & 7)) * 80 +
                                      ((lane >> 3) & 1) * 16);

    const int NC = K >> 5;

    load_stage(sb, 0);

    for (int it = 0; it < NC; it++) {
        if (it + 1 < NC) {
            load_stage(sb + ((it + 1) & 1) * F2_STAGE, (it + 1) << 5);
            CP_WAIT(1);
        } else {
            CP_WAIT(0);
        }
        __syncthreads();

        const uint32_t st  = sb + (it & 1) * F2_STAGE;
        const uint32_t aHb = st + wm * 32 * 80 + a_off;
        const uint32_t aLb = st + F2_TILE + wm * 32 * 80 + a_off;
        const uint32_t bBb = st + 2 * F2_TILE + wn * 64 * 80 + b_off;

#pragma unroll
        for (int kk = 0; kk < 2; kk++) {
            const uint32_t ko = kk * 32;
            uint32_t ah[2][4], al[2][4], bb[4][4];
#pragma unroll
            for (int mt = 0; mt < 2; mt++) {
                LDSM4(ah[mt], aHb + mt * 16 * 80 + ko);
                LDSM4(al[mt], aLb + mt * 16 * 80 + ko);
            }
#pragma unroll
            for (int bt = 0; bt < 4; bt++)
                LDSM4(bb[bt], bBb + bt * 16 * 80 + ko);
            // term-major for accumulator reuse distance
#pragma unroll
            for (int mt = 0; mt < 2; mt++)
#pragma unroll
                for (int nt = 0; nt < 8; nt++) {
                    const int bt = nt >> 1, hh = (nt & 1) << 1;
                    MMA_FP16(acc[mt][nt], ah[mt], bb[bt][hh], bb[bt][hh + 1]);
                }
#pragma unroll
            for (int mt = 0; mt < 2; mt++)
#pragma unroll
                for (int nt = 0; nt < 8; nt++) {
                    const int bt = nt >> 1, hh = (nt & 1) << 1;
                    MMA_FP16(acc[mt][nt], al[mt], bb[bt][hh], bb[bt][hh + 1]);
                }
        }
        __syncthreads();
    }

    const int r0 = bm + wm * 32 + (lane >> 2);
    const int c0 = bn + wn * 64 + (lane & 3) * 2;
#pragma unroll
    for (int mt = 0; mt < 2; mt++)
#pragma unroll
        for (int nt = 0; nt < 8; nt++) {
            float* p0 = C + (size_t)(r0 + mt * 16) * N + c0 + nt * 8;
            *(float2*)p0                   = make_float2(acc[mt][nt][0], acc[mt][nt][1]);
            *(float2*)(p0 + (size_t)8 * N) = make_float2(acc[mt][nt][2], acc[mt][nt][3]);
        }
}

// ---------------- fp16 single-term GEMM (final projection) ----------------
#define T3_TILE_A 5120            // 64 * 80
#define T3_STAGE  15360           // A(5120) + B(10240)
#define T3_SMEM   (2 * T3_STAGE)  // 30720

__global__ __launch_bounds__(256, 3)
void gemm_fp16(const __half* __restrict__ A, const __half* __restrict__ B,
               float* __restrict__ C, int M, int N, int K) {
    extern __shared__ __align__(128) char smem[];
    const uint32_t sb = smem_u32(smem);
    const int tid  = threadIdx.x;
    const int lane = tid & 31;
    const int wid  = tid >> 5;
    const int wm   = wid & 1;          // 2 warps in M
    const int wn   = wid >> 1;         // 4 warps in N
    const int bm   = blockIdx.y * 64;
    const int bn   = blockIdx.x * 128;

    const __half* srcA = A + (size_t)bm * K;
    const __half* srcB = B + (size_t)bn * K;

    float acc[2][4][4];
#pragma unroll
    for (int mt = 0; mt < 2; mt++)
#pragma unroll
        for (int nt = 0; nt < 4; nt++)
#pragma unroll
            for (int q = 0; q < 4; q++) acc[mt][nt][q] = 0.f;

    const uint32_t a_off = (uint32_t)((lane & 15) * 80 + (lane >> 4) * 16);
    const uint32_t b_off = (uint32_t)((((lane >> 4) << 3) + (lane & 7)) * 80 +
                                      ((lane >> 3) & 1) * 16);

    const int NC = K >> 5;

    auto load_stage = [&](uint32_t stb, int k0) {
#pragma unroll
        for (int i = 0; i < 3; i++) {
            int c = i * 256 + tid;
            if (c < 256) {
                int r = c >> 2, j = c & 3;
                CP_ASYNC16(stb + r * 80 + j * 16,
                           srcA + (size_t)r * K + k0 + j * 8);
            } else {
                int c2 = c - 256;
                int r = c2 >> 2, j = c2 & 3;
                CP_ASYNC16(stb + T3_TILE_A + r * 80 + j * 16,
                           srcB + (size_t)r * K + k0 + j * 8);
            }
        }
        CP_COMMIT();
    };

    load_stage(sb, 0);

    for (int it = 0; it < NC; it++) {
        if (it + 1 < NC) {
            load_stage(sb + ((it + 1) & 1) * T3_STAGE, (it + 1) << 5);
            CP_WAIT(1);
        } else {
            CP_WAIT(0);
        }
        __syncthreads();

        const uint32_t st = sb + (it & 1) * T3_STAGE;
        const uint32_t aB = st + wm * 32 * 80 + a_off;
        const uint32_t bB = st + T3_TILE_A + wn * 32 * 80 + b_off;

#pragma unroll
        for (int kk = 0; kk < 2; kk++) {
            const uint32_t ko = kk * 32;
            uint32_t ah[2][4], bb[2][4];
#pragma unroll
            for (int mt = 0; mt < 2; mt++)
                LDSM4(ah[mt], aB + mt * 16 * 80 + ko);
#pragma unroll
            for (int bt = 0; bt < 2; bt++)
                LDSM4(bb[bt], bB + bt * 16 * 80 + ko);
#pragma unroll
            for (int mt = 0; mt < 2; mt++)
#pragma unroll
                for (int nt = 0; nt < 4; nt++) {
                    const int bt = nt >> 1, hh = (nt & 1) << 1;
                    MMA_FP16(acc[mt][nt], ah[mt], bb[bt][hh], bb[bt][hh + 1]);
                }
        }
        __syncthreads();
    }

    const int r0 = bm + wm * 32 + (lane >> 2);
    const int c0 = bn + wn * 32 + (lane & 3) * 2;
#pragma unroll
    for (int mt = 0; mt < 2; mt++)
#pragma unroll
        for (int nt = 0; nt < 4; nt++) {
            float* p0 = C + (size_t)(r0 + mt * 16) * N + c0 + nt * 8;
            *(float2*)p0                   = make_float2(acc[mt][nt][0], acc[mt][nt][1]);
            *(float2*)(p0 + (size_t)8 * N) = make_float2(acc[mt][nt][2], acc[mt][nt][3]);
        }
}

// ---------------- fp32 -> fp16 hi/lo split ----------------
__device__ __forceinline__ void split_fp16(float v, __half& h, __half& l) {
    h = __float2half_rn(v);
    l = __float2half_rn(v - __half2float(h));
}

// fused prep: split x (fp16 hi/lo); W_in, W_out -> fp16; pack [W_dt;W_x;0] -> fp16
#define N_JOB0 (M_ROWS * DM)
#define N_JOB1 (N_XZ * DM)
#define N_JOB2 (DM * DI)
#define N_JOB3 (N_COMB * DI)
#define N_PREP (N_JOB0 + N_JOB1 + N_JOB2 + N_JOB3)
__global__ void prep_k(const float* __restrict__ x, const float* __restrict__ Win,
                       const float* __restrict__ Wout,
                       const float* __restrict__ Wdt, const float* __restrict__ Wx) {
    int idx = blockIdx.x * 256 + threadIdx.x;
    if (idx < N_JOB0) {
        split_fp16(x[idx], g_xh[idx], g_xl[idx]);
        return;
    }
    idx -= N_JOB0;
    if (idx < N_JOB1) {
        g_wi16[idx] = __float2half_rn(Win[idx]);
        return;
    }
    idx -= N_JOB1;
    if (idx < N_JOB2) {
        g_wo16[idx] = __float2half_rn(Wout[idx]);
        return;
    }
    idx -= N_JOB2;
    if (idx < N_JOB3) {
        int row = idx / DI, col = idx - row * DI;
        float v = 0.f;
        if (row < DI)           v = Wdt[idx];
        else if (row < DI + 32) v = Wx[(row - DI) * DI + col];
        g_wc16[idx] = __float2half_rn(v);
    }
}

// ---------------- conv + SiLU (fp32 + fp16 split outputs) ----------------
__global__ void conv_silu_k(const float* __restrict__ Wc) {
    int idx = blockIdx.x * 256 + threadIdx.x;
    if (idx >= M_ROWS * DI) return;
    int d = idx % DI, m = idx / DI, l = m & (L_SEQ - 1);
    float w0 = Wc[d*4+0], w1 = Wc[d*4+1], w2 = Wc[d*4+2], w3 = Wc[d*4+3];
    float s = g_xz[(size_t)m * N_XZ + d] * w3;
    if (l >= 1) s = fmaf(g_xz[(size_t)(m-1) * N_XZ + d], w2, s);
    if (l >= 2) s = fmaf(g_xz[(size_t)(m-2) * N_XZ + d], w1, s);
    if (l >= 3) s = fmaf(g_xz[(size_t)(m-3) * N_XZ + d], w0, s);
    float v = __fdividef(s, 1.f + __expf(-s));
    g_xc[idx] = v;
    split_fp16(v, g_xch[idx], g_xcl[idx]);
}

// ---------------- scan helpers ----------------
__device__ __forceinline__ void pow16(float p, float* pw) {
    pw[0]=p;          pw[1]=p*p;        pw[2]=pw[1]*p;     pw[3]=pw[1]*pw[1];
    pw[4]=pw[3]*p;    pw[5]=pw[3]*pw[1];pw[6]=pw[3]*pw[2]; pw[7]=pw[3]*pw[3];
    pw[8]=pw[7]*p;    pw[9]=pw[7]*pw[1];pw[10]=pw[7]*pw[2];pw[11]=pw[7]*pw[3];
    pw[12]=pw[7]*pw[4];pw[13]=pw[7]*pw[5];pw[14]=pw[7]*pw[6];pw[15]=pw[7]*pw[7];
}
__device__ __forceinline__ bool geo_check(const float* Alog, float* A) {
#pragma unroll
    for (int s = 0; s < DS; s++) A[s] = -__expf(Alog[s]);
    bool geo = true;
#pragma unroll
    for (int s = 0; s < DS; s++)
        geo = geo && (fabsf(A[s] - (float)(s + 1) * A[0]) <= 1e-5f * fabsf(A[s]));
    return geo;
}
__device__ __forceinline__ float softplus_f(float x) {
    return (x > 20.f) ? x : log1pf(__expf(x));
}

// ---------------- scan phase A: local scans ----------------
__global__ __launch_bounds__(128)
void scan_a(const float* __restrict__ Alog, const float* __restrict__ bdt) {
    __shared__ float sBC[CL * 32];
    const int d = blockIdx.x * 128 + threadIdx.x;
    const int c = blockIdx.y, b = blockIdx.z;
    const int m0 = b * L_SEQ + c * CL;
    for (int e = threadIdx.x; e < CL * 32; e += 128) {
        int l = e >> 5, q = e & 31;
        sBC[e] = g_dx[(size_t)(m0 + l) * N_COMB + DI + q];
    }
    __syncthreads();

    float A[DS];
    const bool geo = geo_check(Alog, A);
    const float bd = bdt[d];
    float h[DS];
#pragma unroll
    for (int s = 0; s < DS; s++) h[s] = 0.f;
    const size_t base = ((size_t)(b * CCH + c) * DS) * DI + d;

    if (geo) {
        const float A0 = A[0];
        float pp = 1.f;
        for (int l = 0; l < CL; l++) {
            const size_t m = m0 + l;
            float dt = softplus_f(g_dx[m * N_COMB + d] + bd);
            float p = __expf(A0 * dt);
            g_p[m * DI + d] = p;
            pp *= p;
            float pw[DS]; pow16(p, pw);
            float y0=0.f, y1=0.f, y2=0.f, y3=0.f;
#pragma unroll
            for (int s = 0; s < DS; s++) {
                h[s] = fmaf(pw[s], h[s], dt * sBC[l * 32 + s]);
                float t = h[s] * sBC[l * 32 + 16 + s];
                if ((s&3)==0) y0+=t; else if ((s&3)==1) y1+=t;
                else if ((s&3)==2) y2+=t; else y3+=t;
            }
            g_yp[m * DI + d] = (y0 + y1) + (y2 + y3);
        }
        float dw[DS]; pow16(pp, dw);
#pragma unroll
        for (int s = 0; s < DS; s++) {
            g_cdec[base + (size_t)s * DI] = dw[s];
            g_hend[base + (size_t)s * DI] = h[s];
        }
    } else {
        float dec[DS];
#pragma unroll
        for (int s = 0; s < DS; s++) dec[s] = 1.f;
        for (int l = 0; l < CL; l++) {
            const size_t m = m0 + l;
            float dt = softplus_f(g_dx[m * N_COMB + d] + bd);
            float y0=0.f, y1=0.f, y2=0.f, y3=0.f;
#pragma unroll
            for (int s = 0; s < DS; s++) {
                float dA = __expf(A[s] * dt);
                dec[s] *= dA;
                h[s] = fmaf(dA, h[s], dt * sBC[l * 32 + s]);
                float t = h[s] * sBC[l * 32 + 16 + s];
                if ((s&3)==0) y0+=t; else if ((s&3)==1) y1+=t;
                else if ((s&3)==2) y2+=t; else y3+=t;
            }
            g_yp[m * DI + d] = (y0 + y1) + (y2 + y3);
        }
#pragma unroll
        for (int s = 0; s < DS; s++) {
            g_cdec[base + (size_t)s * DI] = dec[s];
            g_hend[base + (size_t)s * DI] = h[s];
        }
    }
}

// ---------------- scan phase B: chunk combine ----------------
__global__ __launch_bounds__(128)
void scan_b() {
    const int d = blockIdx.x * 128 + threadIdx.x;
    const int b = blockIdx.y;
    float H[DS];
#pragma unroll
    for (int s = 0; s < DS; s++) H[s] = 0.f;
    for (int c = 0; c < CCH; c++) {
        const size_t base = ((size_t)(b * CCH + c) * DS) * DI + d;
#pragma unroll
        for (int s = 0; s < DS; s++) {
            g_h0[base + (size_t)s * DI] = H[s];
            H[s] = fmaf(g_cdec[base + (size_t)s * DI], H[s],
                        g_hend[base + (size_t)s * DI]);
        }
    }
}

// ---------------- scan phase C: correction + gate + fp16 out ----------------
__global__ __launch_bounds__(128)
void scan_c(const float* __restrict__ Alog, const float* __restrict__ Dp,
            const float* __restrict__ bdt) {
    __shared__ float sC[CL * 16];
    const int d = blockIdx.x * 128 + threadIdx.x;
    const int c = blockIdx.y, b = blockIdx.z;
    const int m0 = b * L_SEQ + c * CL;
    for (int e = threadIdx.x; e < CL * 16; e += 128) {
        int l = e >> 4, q = e & 15;
        sC[e] = g_dx[(size_t)(m0 + l) * N_COMB + DI + 16 + q];
    }
    __syncthreads();

    float A[DS];
    const bool geo = geo_check(Alog, A);
    const float Dd = Dp[d];
    const float bd = bdt[d];
    float H0[DS];
    const size_t base = ((size_t)(b * CCH + c) * DS) * DI + d;
#pragma unroll
    for (int s = 0; s < DS; s++) H0[s] = g_h0[base + (size_t)s * DI];

    if (geo) {
        float run = 1.f;
        for (int l = 0; l < CL; l++) {
            const size_t m = m0 + l;
            run *= g_p[m * DI + d];
            float rw[DS]; pow16(run, rw);
            float corr = 0.f;
#pragma unroll
            for (int s = 0; s < DS; s++)
                corr = fmaf(rw[s] * H0[s], sC[l * 16 + s], corr);
            float y = g_yp[m * DI + d] + corr;
            float z = g_xz[m * N_XZ + DI + d];
            float o = (y + Dd * g_xc[m * DI + d]) *
                      __fdividef(z, 1.f + __expf(-z));
            g_y16[m * DI + d] = __float2half_rn(o);
        }
    } else {
        float run[DS];
#pragma unroll
        for (int s = 0; s < DS; s++) run[s] = 1.f;
        for (int l = 0; l < CL; l++) {
            const size_t m = m0 + l;
            float dt = softplus_f(g_dx[m * N_COMB + d] + bd);
            float corr = 0.f;
#pragma unroll
            for (int s = 0; s < DS; s++) {
                run[s] *= __expf(A[s] * dt);
                corr = fmaf(run[s] * H0[s], sC[l * 16 + s], corr);
            }
            float y = g_yp[m * DI + d] + corr;
            float z = g_xz[m * N_XZ + DI + d];
            float o = (y + Dd * g_xc[m * DI + d]) *
                      __fdividef(z, 1.f + __expf(-z));
            g_y16[m * DI + d] = __float2half_rn(o);
        }
    }
}

// ---------------- launch ----------------
extern "C" void kernel_launch(void* const* d_in, const int* in_sizes, int n_in,
                              void* d_out, int out_size) {
    const float* x      = (const float*)d_in[0];
    const float* W_in   = (const float*)d_in[1];
    const float* W_conv = (const float*)d_in[2];
    const float* W_x    = (const float*)d_in[3];
    const float* W_dt   = (const float*)d_in[4];
    const float* b_dt   = (const float*)d_in[5];
    const float* A_log  = (const float*)d_in[6];
    const float* Dp     = (const float*)d_in[7];
    const float* W_out  = (const float*)d_in[8];
    float* out = (float*)d_out;

    cudaFuncSetAttribute(gemm_f16x2, cudaFuncAttributeMaxDynamicSharedMemorySize,
                         F2_SMEM);
    cudaFuncSetAttribute(gemm_fp16, cudaFuncAttributeMaxDynamicSharedMemorySize,
                         T3_SMEM);

    float *xz, *dx;
    __half *xh, *xl, *wi16, *wc16, *xch, *xcl, *y16, *wo16;
    cudaGetSymbolAddress((void**)&xz,   g_xz);
    cudaGetSymbolAddress((void**)&dx,   g_dx);
    cudaGetSymbolAddress((void**)&xh,   g_xh);   cudaGetSymbolAddress((void**)&xl,   g_xl);
    cudaGetSymbolAddress((void**)&wi16, g_wi16); cudaGetSymbolAddress((void**)&wc16, g_wc16);
    cudaGetSymbolAddress((void**)&xch,  g_xch);  cudaGetSymbolAddress((void**)&xcl,  g_xcl);
    cudaGetSymbolAddress((void**)&y16,  g_y16);  cudaGetSymbolAddress((void**)&wo16, g_wo16);

    // fused prep
    prep_k<<<(N_PREP + 255)/256, 256>>>(x, W_in, W_out, W_dt, W_x);

    // xz = x @ W_in^T   (fp16 2-term)
    gemm_f16x2<<<dim3(N_XZ/128, M_ROWS/128), 256, F2_SMEM>>>(
        xh, xl, wi16, xz, M_ROWS, N_XZ, DM);
    // xc = silu(conv(xz[:, :di]))
    conv_silu_k<<<(M_ROWS*DI + 255)/256, 256>>>(W_conv);
    // dx = xc @ [W_dt;W_x;0]^T   (fp16 2-term)
    gemm_f16x2<<<dim3(N_COMB/128, M_ROWS/128), 256, F2_SMEM>>>(
        xch, xcl, wc16, dx, M_ROWS, N_COMB, DI);
    // chunked selective scan
    scan_a<<<dim3(DI/128, CCH, BATCH), 128>>>(A_log, b_dt);
    scan_b<<<dim3(DI/128, BATCH), 128>>>();
    scan_c<<<dim3(DI/128, CCH, BATCH), 128>>>(A_log, Dp, b_dt);
    // out = y @ W_out^T  (fp16 single-term)
    gemm_fp16<<<dim3(DM/128, M_ROWS/64), 256, T3_SMEM>>>(
        y16, wo16, out, M_ROWS, DM, DI);
}

// round 8
// speedup vs baseline: 1.3369x; 1.0382x over previous
#include <cuda_runtime.h>
#include <cuda_bf16.h>
#include <cuda_fp16.h>
#include <math.h>
#include <stdint.h>

// ---------------- problem sizes ----------------
#define L_SEQ  2048
#define BATCH  2
#define DM     768
#define DI     1536
#define DS     16
#define M_ROWS (BATCH * L_SEQ)   // 4096
#define N_XZ   (2 * DI)          // 3072
#define N_COMB 1664              // 1536 + 32, padded to 13*128
#define CCH    32                // scan chunks
#define CL     64                // chunk length

typedef __nv_bfloat16 bf16;

// ---------------- scratch globals ----------------
__device__ __align__(128) float g_xz[M_ROWS * N_XZ];
__device__ __align__(128) float g_dx[M_ROWS * N_COMB];
__device__ __align__(128) float g_xc[M_ROWS * DI];
__device__ __align__(128) float g_p [M_ROWS * DI];
__device__ __align__(128) float g_yp[M_ROWS * DI];

__device__ __align__(128) __half g_xh [M_ROWS * DM],  g_xl [M_ROWS * DM];
__device__ __align__(128) __half g_wi16[N_XZ * DM];
__device__ __align__(128) __half g_wc16[N_COMB * DI];
__device__ __align__(128) __half g_xch[M_ROWS * DI],  g_xcl[M_ROWS * DI];
__device__ __align__(128) __half g_y16 [M_ROWS * DI];
__device__ __align__(128) __half g_wo16[DM * DI];

__device__ __align__(128) float g_cdec[BATCH * CCH * DS * DI];
__device__ __align__(128) float g_hend[BATCH * CCH * DS * DI];
__device__ __align__(128) float g_h0  [BATCH * CCH * DS * DI];

// ---------------- PTX helpers (plain sm_80+ PTX; NO tcgen05) --------
__device__ __forceinline__ uint32_t smem_u32(const void* p) {
    uint32_t a;
    asm("{ .reg .u64 t; cvta.to.shared.u64 t, %1; cvt.u32.u64 %0, t; }" : "=r"(a) : "l"(p));
    return a;
}
#define CP_ASYNC16(dst, src) \
    asm volatile("cp.async.cg.shared.global [%0], [%1], 16;" :: "r"(dst), "l"(src))
#define CP_COMMIT() asm volatile("cp.async.commit_group;")
#define CP_WAIT(n)  asm volatile("cp.async.wait_group %0;" :: "n"(n))
#define LDSM4(r, a) \
    asm volatile("ldmatrix.sync.aligned.m8n8.x4.shared.b16 {%0,%1,%2,%3}, [%4];" \
                 : "=r"((r)[0]), "=r"((r)[1]), "=r"((r)[2]), "=r"((r)[3]) : "r"(a))
#define MMA_FP16(c, a, b0, b1) \
    asm volatile("mma.sync.aligned.m16n8k16.row.col.f32.f16.f16.f32 " \
                 "{%0,%1,%2,%3}, {%4,%5,%6,%7}, {%8,%9}, {%0,%1,%2,%3};" \
                 : "+f"((c)[0]), "+f"((c)[1]), "+f"((c)[2]), "+f"((c)[3]) \
                 : "r"((a)[0]), "r"((a)[1]), "r"((a)[2]), "r"((a)[3]), \
                   "r"(b0), "r"(b1))

// ---------------- fp16 2-term GEMM: C[M,N] = (Ah+Al) B^T ----------------
#define F2_TILE  10240            // 128 rows * 80 bytes
#define F2_STAGE 30720            // Ah, Al, B
#define F2_SMEM  (2 * F2_STAGE)   // 61440

__global__ __launch_bounds__(256, 2)
void gemm_f16x2(const __half* __restrict__ Ah, const __half* __restrict__ Al,
                const __half* __restrict__ B, float* __restrict__ C,
                int M, int N, int K) {
    extern __shared__ __align__(128) char smem[];
    const uint32_t sb = smem_u32(smem);
    const int tid  = threadIdx.x;
    const int lane = tid & 31;
    const int wid  = tid >> 5;
    const int wm   = wid & 3;
    const int wn   = wid >> 2;
    const int bm   = blockIdx.y * 128;
    const int bn   = blockIdx.x * 128;

    const __half* srcs[3] = { Ah + (size_t)bm * K, Al + (size_t)bm * K,
                              B + (size_t)bn * K };

    auto load_stage = [&](uint32_t stb, int k0) {
#pragma unroll
        for (int i = 0; i < 6; i++) {
            const int c = i * 256 + tid;
            const int t = c >> 9, w = c & 511, r = w >> 2, j = w & 3;
            CP_ASYNC16(stb + t * F2_TILE + r * 80 + j * 16,
                       srcs[t] + (size_t)r * K + k0 + j * 8);
        }
        CP_COMMIT();
    };

    float acc[2][8][4];
#pragma unroll
    for (int mt = 0; mt < 2; mt++)
#pragma unroll
        for (int nt = 0; nt < 8; nt++)
#pragma unroll
            for (int q = 0; q < 4; q++) acc[mt][nt][q] = 0.f;

    const uint32_t a_off = (uint32_t)((lane & 15) * 80 + (lane >> 4) * 16);
    const uint32_t b_off = (uint32_t)((((lane >> 4) << 3) + (lane & 7)) * 80 +
                                      ((lane >> 3) & 1) * 16);

    const int NC = K >> 5;
    load_stage(sb, 0);

    for (int it = 0; it < NC; it++) {
        if (it + 1 < NC) {
            load_stage(sb + ((it + 1) & 1) * F2_STAGE, (it + 1) << 5);
            CP_WAIT(1);
        } else {
            CP_WAIT(0);
        }
        __syncthreads();

        const uint32_t st  = sb + (it & 1) * F2_STAGE;
        const uint32_t aHb = st + wm * 32 * 80 + a_off;
        const uint32_t aLb = st + F2_TILE + wm * 32 * 80 + a_off;
        const uint32_t bBb = st + 2 * F2_TILE + wn * 64 * 80 + b_off;

#pragma unroll
        for (int kk = 0; kk < 2; kk++) {
            const uint32_t ko = kk * 32;
            uint32_t ah[2][4], al[2][4], bb[4][4];
#pragma unroll
            for (int mt = 0; mt < 2; mt++) {
                LDSM4(ah[mt], aHb + mt * 16 * 80 + ko);
                LDSM4(al[mt], aLb + mt * 16 * 80 + ko);
            }
#pragma unroll
            for (int bt = 0; bt < 4; bt++)
                LDSM4(bb[bt], bBb + bt * 16 * 80 + ko);
#pragma unroll
            for (int mt = 0; mt < 2; mt++)
#pragma unroll
                for (int nt = 0; nt < 8; nt++) {
                    const int bt = nt >> 1, hh = (nt & 1) << 1;
                    MMA_FP16(acc[mt][nt], ah[mt], bb[bt][hh], bb[bt][hh + 1]);
                }
#pragma unroll
            for (int mt = 0; mt < 2; mt++)
#pragma unroll
                for (int nt = 0; nt < 8; nt++) {
                    const int bt = nt >> 1, hh = (nt & 1) << 1;
                    MMA_FP16(acc[mt][nt], al[mt], bb[bt][hh], bb[bt][hh + 1]);
                }
        }
        __syncthreads();
    }

    const int r0 = bm + wm * 32 + (lane >> 2);
    const int c0 = bn + wn * 64 + (lane & 3) * 2;
#pragma unroll
    for (int mt = 0; mt < 2; mt++)
#pragma unroll
        for (int nt = 0; nt < 8; nt++) {
            float* p0 = C + (size_t)(r0 + mt * 16) * N + c0 + nt * 8;
            *(float2*)p0                   = make_float2(acc[mt][nt][0], acc[mt][nt][1]);
            *(float2*)(p0 + (size_t)8 * N) = make_float2(acc[mt][nt][2], acc[mt][nt][3]);
        }
}

// ---------------- fp16 single-term GEMM (final projection) ----------------
#define T3_TILE_A 5120
#define T3_STAGE  15360
#define T3_SMEM   (2 * T3_STAGE)

__global__ __launch_bounds__(256, 3)
void gemm_fp16(const __half* __restrict__ A, const __half* __restrict__ B,
               float* __restrict__ C, int M, int N, int K) {
    extern __shared__ __align__(128) char smem[];
    const uint32_t sb = smem_u32(smem);
    const int tid  = threadIdx.x;
    const int lane = tid & 31;
    const int wid  = tid >> 5;
    const int wm   = wid & 1;
    const int wn   = wid >> 1;
    const int bm   = blockIdx.y * 64;
    const int bn   = blockIdx.x * 128;

    const __half* srcA = A + (size_t)bm * K;
    const __half* srcB = B + (size_t)bn * K;

    float acc[2][4][4];
#pragma unroll
    for (int mt = 0; mt < 2; mt++)
#pragma unroll
        for (int nt = 0; nt < 4; nt++)
#pragma unroll
            for (int q = 0; q < 4; q++) acc[mt][nt][q] = 0.f;

    const uint32_t a_off = (uint32_t)((lane & 15) * 80 + (lane >> 4) * 16);
    const uint32_t b_off = (uint32_t)((((lane >> 4) << 3) + (lane & 7)) * 80 +
                                      ((lane >> 3) & 1) * 16);

    const int NC = K >> 5;

    auto load_stage = [&](uint32_t stb, int k0) {
#pragma unroll
        for (int i = 0; i < 3; i++) {
            int c = i * 256 + tid;
            if (c < 256) {
                int r = c >> 2, j = c & 3;
                CP_ASYNC16(stb + r * 80 + j * 16,
                           srcA + (size_t)r * K + k0 + j * 8);
            } else {
                int c2 = c - 256;
                int r = c2 >> 2, j = c2 & 3;
                CP_ASYNC16(stb + T3_TILE_A + r * 80 + j * 16,
                           srcB + (size_t)r * K + k0 + j * 8);
            }
        }
        CP_COMMIT();
    };

    load_stage(sb, 0);

    for (int it = 0; it < NC; it++) {
        if (it + 1 < NC) {
            load_stage(sb + ((it + 1) & 1) * T3_STAGE, (it + 1) << 5);
            CP_WAIT(1);
        } else {
            CP_WAIT(0);
        }
        __syncthreads();

        const uint32_t st = sb + (it & 1) * T3_STAGE;
        const uint32_t aB = st + wm * 32 * 80 + a_off;
        const uint32_t bB = st + T3_TILE_A + wn * 32 * 80 + b_off;

#pragma unroll
        for (int kk = 0; kk < 2; kk++) {
            const uint32_t ko = kk * 32;
            uint32_t ah[2][4], bb[2][4];
#pragma unroll
            for (int mt = 0; mt < 2; mt++)
                LDSM4(ah[mt], aB + mt * 16 * 80 + ko);
#pragma unroll
            for (int bt = 0; bt < 2; bt++)
                LDSM4(bb[bt], bB + bt * 16 * 80 + ko);
#pragma unroll
            for (int mt = 0; mt < 2; mt++)
#pragma unroll
                for (int nt = 0; nt < 4; nt++) {
                    const int bt = nt >> 1, hh = (nt & 1) << 1;
                    MMA_FP16(acc[mt][nt], ah[mt], bb[bt][hh], bb[bt][hh + 1]);
                }
        }
        __syncthreads();
    }

    const int r0 = bm + wm * 32 + (lane >> 2);
    const int c0 = bn + wn * 32 + (lane & 3) * 2;
#pragma unroll
    for (int mt = 0; mt < 2; mt++)
#pragma unroll
        for (int nt = 0; nt < 4; nt++) {
            float* p0 = C + (size_t)(r0 + mt * 16) * N + c0 + nt * 8;
            *(float2*)p0                   = make_float2(acc[mt][nt][0], acc[mt][nt][1]);
            *(float2*)(p0 + (size_t)8 * N) = make_float2(acc[mt][nt][2], acc[mt][nt][3]);
        }
}

// ---------------- fp32 -> fp16 hi/lo split ----------------
__device__ __forceinline__ void split_fp16(float v, __half& h, __half& l) {
    h = __float2half_rn(v);
    l = __float2half_rn(v - __half2float(h));
}

// fused prep
#define N_JOB0 (M_ROWS * DM)
#define N_JOB1 (N_XZ * DM)
#define N_JOB2 (DM * DI)
#define N_JOB3 (N_COMB * DI)
#define N_PREP (N_JOB0 + N_JOB1 + N_JOB2 + N_JOB3)
__global__ void prep_k(const float* __restrict__ x, const float* __restrict__ Win,
                       const float* __restrict__ Wout,
                       const float* __restrict__ Wdt, const float* __restrict__ Wx) {
    int idx = blockIdx.x * 256 + threadIdx.x;
    if (idx < N_JOB0) {
        split_fp16(x[idx], g_xh[idx], g_xl[idx]);
        return;
    }
    idx -= N_JOB0;
    if (idx < N_JOB1) {
        g_wi16[idx] = __float2half_rn(Win[idx]);
        return;
    }
    idx -= N_JOB1;
    if (idx < N_JOB2) {
        g_wo16[idx] = __float2half_rn(Wout[idx]);
        return;
    }
    idx -= N_JOB2;
    if (idx < N_JOB3) {
        int row = idx / DI, col = idx - row * DI;
        float v = 0.f;
        if (row < DI)           v = Wdt[idx];
        else if (row < DI + 32) v = Wx[(row - DI) * DI + col];
        g_wc16[idx] = __float2half_rn(v);
    }
}

// ---------------- conv + SiLU ----------------
__global__ void conv_silu_k(const float* __restrict__ Wc) {
    int idx = blockIdx.x * 256 + threadIdx.x;
    if (idx >= M_ROWS * DI) return;
    int d = idx % DI, m = idx / DI, l = m & (L_SEQ - 1);
    float w0 = Wc[d*4+0], w1 = Wc[d*4+1], w2 = Wc[d*4+2], w3 = Wc[d*4+3];
    float s = g_xz[(size_t)m * N_XZ + d] * w3;
    if (l >= 1) s = fmaf(g_xz[(size_t)(m-1) * N_XZ + d], w2, s);
    if (l >= 2) s = fmaf(g_xz[(size_t)(m-2) * N_XZ + d], w1, s);
    if (l >= 3) s = fmaf(g_xz[(size_t)(m-3) * N_XZ + d], w0, s);
    float v = __fdividef(s, 1.f + __expf(-s));
    g_xc[idx] = v;
    split_fp16(v, g_xch[idx], g_xcl[idx]);
}

// ---------------- scan helpers ----------------
__device__ __forceinline__ void pow16(float p, float* pw) {
    pw[0]=p;          pw[1]=p*p;        pw[2]=pw[1]*p;     pw[3]=pw[1]*pw[1];
    pw[4]=pw[3]*p;    pw[5]=pw[3]*pw[1];pw[6]=pw[3]*pw[2]; pw[7]=pw[3]*pw[3];
    pw[8]=pw[7]*p;    pw[9]=pw[7]*pw[1];pw[10]=pw[7]*pw[2];pw[11]=pw[7]*pw[3];
    pw[12]=pw[7]*pw[4];pw[13]=pw[7]*pw[5];pw[14]=pw[7]*pw[6];pw[15]=pw[7]*pw[7];
}
__device__ __forceinline__ bool geo_check(const float* Alog, float* A) {
#pragma unroll
    for (int s = 0; s < DS; s++) A[s] = -__expf(Alog[s]);
    bool geo = true;
#pragma unroll
    for (int s = 0; s < DS; s++)
        geo = geo && (fabsf(A[s] - (float)(s + 1) * A[0]) <= 1e-5f * fabsf(A[s]));
    return geo;
}
__device__ __forceinline__ float softplus_f(float x) {
    return (x > 20.f) ? x : log1pf(__expf(x));
}

#define PF 8   // prefetch batch

// ---------------- scan phase A: local scans (batched prefetch) ----------------
__global__ __launch_bounds__(128)
void scan_a(const float* __restrict__ Alog, const float* __restrict__ bdt) {
    __shared__ float sBC[CL * 32];
    const int d = blockIdx.x * 128 + threadIdx.x;
    const int c = blockIdx.y, b = blockIdx.z;
    const int m0 = b * L_SEQ + c * CL;
    for (int e = threadIdx.x; e < CL * 32; e += 128) {
        int l = e >> 5, q = e & 31;
        sBC[e] = g_dx[(size_t)(m0 + l) * N_COMB + DI + q];
    }
    __syncthreads();

    float A[DS];
    const bool geo = geo_check(Alog, A);
    const float bd = bdt[d];
    float h[DS];
#pragma unroll
    for (int s = 0; s < DS; s++) h[s] = 0.f;
    const size_t base = ((size_t)(b * CCH + c) * DS) * DI + d;

    // prefetch delta column in batches of PF
    float pf[PF];
#pragma unroll
    for (int i = 0; i < PF; i++)
        pf[i] = g_dx[(size_t)(m0 + i) * N_COMB + d];

    if (geo) {
        const float A0 = A[0];
        float pp = 1.f;
        for (int l0 = 0; l0 < CL; l0 += PF) {
            float cur[PF];
#pragma unroll
            for (int i = 0; i < PF; i++) cur[i] = pf[i];
            if (l0 + PF < CL) {
#pragma unroll
                for (int i = 0; i < PF; i++)
                    pf[i] = g_dx[(size_t)(m0 + l0 + PF + i) * N_COMB + d];
            }
#pragma unroll
            for (int u = 0; u < PF; u++) {
                const int l = l0 + u;
                const size_t m = m0 + l;
                float dt = softplus_f(cur[u] + bd);
                float p = __expf(A0 * dt);
                g_p[m * DI + d] = p;
                pp *= p;
                float pw[DS]; pow16(p, pw);
                float y0=0.f, y1=0.f, y2=0.f, y3=0.f;
#pragma unroll
                for (int s = 0; s < DS; s++) {
                    h[s] = fmaf(pw[s], h[s], dt * sBC[l * 32 + s]);
                    float t = h[s] * sBC[l * 32 + 16 + s];
                    if ((s&3)==0) y0+=t; else if ((s&3)==1) y1+=t;
                    else if ((s&3)==2) y2+=t; else y3+=t;
                }
                g_yp[m * DI + d] = (y0 + y1) + (y2 + y3);
            }
        }
        float dw[DS]; pow16(pp, dw);
#pragma unroll
        for (int s = 0; s < DS; s++) {
            g_cdec[base + (size_t)s * DI] = dw[s];
            g_hend[base + (size_t)s * DI] = h[s];
        }
    } else {
        float dec[DS];
#pragma unroll
        for (int s = 0; s < DS; s++) dec[s] = 1.f;
        for (int l0 = 0; l0 < CL; l0 += PF) {
            float cur[PF];
#pragma unroll
            for (int i = 0; i < PF; i++) cur[i] = pf[i];
            if (l0 + PF < CL) {
#pragma unroll
                for (int i = 0; i < PF; i++)
                    pf[i] = g_dx[(size_t)(m0 + l0 + PF + i) * N_COMB + d];
            }
#pragma unroll
            for (int u = 0; u < PF; u++) {
                const int l = l0 + u;
                const size_t m = m0 + l;
                float dt = softplus_f(cur[u] + bd);
                g_p[m * DI + d] = __expf(A[0] * dt);
                float y0=0.f, y1=0.f, y2=0.f, y3=0.f;
#pragma unroll
                for (int s = 0; s < DS; s++) {
                    float dA = __expf(A[s] * dt);
                    dec[s] *= dA;
                    h[s] = fmaf(dA, h[s], dt * sBC[l * 32 + s]);
                    float t = h[s] * sBC[l * 32 + 16 + s];
                    if ((s&3)==0) y0+=t; else if ((s&3)==1) y1+=t;
                    else if ((s&3)==2) y2+=t; else y3+=t;
                }
                g_yp[m * DI + d] = (y0 + y1) + (y2 + y3);
            }
        }
#pragma unroll
        for (int s = 0; s < DS; s++) {
            g_cdec[base + (size_t)s * DI] = dec[s];
            g_hend[base + (size_t)s * DI] = h[s];
        }
    }
}

// ---------------- scan phase B: chunk combine ----------------
__global__ __launch_bounds__(128)
void scan_b() {
    const int d = blockIdx.x * 128 + threadIdx.x;
    const int b = blockIdx.y;
    float H[DS];
#pragma unroll
    for (int s = 0; s < DS; s++) H[s] = 0.f;
    for (int c = 0; c < CCH; c++) {
        const size_t base = ((size_t)(b * CCH + c) * DS) * DI + d;
#pragma unroll
        for (int s = 0; s < DS; s++) {
            g_h0[base + (size_t)s * DI] = H[s];
            H[s] = fmaf(g_cdec[base + (size_t)s * DI], H[s],
                        g_hend[base + (size_t)s * DI]);
        }
    }
}

// ---------------- scan phase C: correction + gate (batched prefetch) --------
__global__ __launch_bounds__(128)
void scan_c(const float* __restrict__ Alog, const float* __restrict__ Dp,
            const float* __restrict__ bdt) {
    __shared__ float sC[CL * 16];
    const int d = blockIdx.x * 128 + threadIdx.x;
    const int c = blockIdx.y, b = blockIdx.z;
    const int m0 = b * L_SEQ + c * CL;
    for (int e = threadIdx.x; e < CL * 16; e += 128) {
        int l = e >> 4, q = e & 15;
        sC[e] = g_dx[(size_t)(m0 + l) * N_COMB + DI + 16 + q];
    }
    __syncthreads();

    float A[DS];
    const bool geo = geo_check(Alog, A);
    const float Dd = Dp[d];
    const float bd = bdt[d];
    float H0[DS];
    const size_t base = ((size_t)(b * CCH + c) * DS) * DI + d;
#pragma unroll
    for (int s = 0; s < DS; s++) H0[s] = g_h0[base + (size_t)s * DI];

    // 4 prefetch streams: p, yp, z, xc
    float pf_p[PF], pf_y[PF], pf_z[PF], pf_x[PF];
#pragma unroll
    for (int i = 0; i < PF; i++) {
        const size_t m = m0 + i;
        pf_p[i] = g_p [m * DI + d];
        pf_y[i] = g_yp[m * DI + d];
        pf_z[i] = g_xz[m * N_XZ + DI + d];
        pf_x[i] = g_xc[m * DI + d];
    }

    if (geo) {
        float run = 1.f;
        for (int l0 = 0; l0 < CL; l0 += PF) {
            float cp[PF], cy[PF], cz[PF], cx[PF];
#pragma unroll
            for (int i = 0; i < PF; i++) {
                cp[i] = pf_p[i]; cy[i] = pf_y[i];
                cz[i] = pf_z[i]; cx[i] = pf_x[i];
            }
            if (l0 + PF < CL) {
#pragma unroll
                for (int i = 0; i < PF; i++) {
                    const size_t m = m0 + l0 + PF + i;
                    pf_p[i] = g_p [m * DI + d];
                    pf_y[i] = g_yp[m * DI + d];
                    pf_z[i] = g_xz[m * N_XZ + DI + d];
                    pf_x[i] = g_xc[m * DI + d];
                }
            }
#pragma unroll
            for (int u = 0; u < PF; u++) {
                const int l = l0 + u;
                const size_t m = m0 + l;
                run *= cp[u];
                float rw[DS]; pow16(run, rw);
                float corr = 0.f;
#pragma unroll
                for (int s = 0; s < DS; s++)
                    corr = fmaf(rw[s] * H0[s], sC[l * 16 + s], corr);
                float y = cy[u] + corr;
                float z = cz[u];
                float o = (y + Dd * cx[u]) * __fdividef(z, 1.f + __expf(-z));
                g_y16[m * DI + d] = __float2half_rn(o);
            }
        }
    } else {
        float run[DS];
#pragma unroll
        for (int s = 0; s < DS; s++) run[s] = 1.f;
        for (int l = 0; l < CL; l++) {
            const size_t m = m0 + l;
            float dt = softplus_f(g_dx[m * N_COMB + d] + bd);
            float corr = 0.f;
#pragma unroll
            for (int s = 0; s < DS; s++) {
                run[s] *= __expf(A[s] * dt);
                corr = fmaf(run[s] * H0[s], sC[l * 16 + s], corr);
            }
            float y = g_yp[m * DI + d] + corr;
            float z = g_xz[m * N_XZ + DI + d];
            float o = (y + Dd * g_xc[m * DI + d]) *
                      __fdividef(z, 1.f + __expf(-z));
            g_y16[m * DI + d] = __float2half_rn(o);
        }
    }
}

// ---------------- launch ----------------
extern "C" void kernel_launch(void* const* d_in, const int* in_sizes, int n_in,
                              void* d_out, int out_size) {
    const float* x      = (const float*)d_in[0];
    const float* W_in   = (const float*)d_in[1];
    const float* W_conv = (const float*)d_in[2];
    const float* W_x    = (const float*)d_in[3];
    const float* W_dt   = (const float*)d_in[4];
    const float* b_dt   = (const float*)d_in[5];
    const float* A_log  = (const float*)d_in[6];
    const float* Dp     = (const float*)d_in[7];
    const float* W_out  = (const float*)d_in[8];
    float* out = (float*)d_out;

    cudaFuncSetAttribute(gemm_f16x2, cudaFuncAttributeMaxDynamicSharedMemorySize,
                         F2_SMEM);
    cudaFuncSetAttribute(gemm_fp16, cudaFuncAttributeMaxDynamicSharedMemorySize,
                         T3_SMEM);

    float *xz, *dx;
    __half *xh, *xl, *wi16, *wc16, *xch, *xcl, *y16, *wo16;
    cudaGetSymbolAddress((void**)&xz,   g_xz);
    cudaGetSymbolAddress((void**)&dx,   g_dx);
    cudaGetSymbolAddress((void**)&xh,   g_xh);   cudaGetSymbolAddress((void**)&xl,   g_xl);
    cudaGetSymbolAddress((void**)&wi16, g_wi16); cudaGetSymbolAddress((void**)&wc16, g_wc16);
    cudaGetSymbolAddress((void**)&xch,  g_xch);  cudaGetSymbolAddress((void**)&xcl,  g_xcl);
    cudaGetSymbolAddress((void**)&y16,  g_y16);  cudaGetSymbolAddress((void**)&wo16, g_wo16);

    prep_k<<<(N_PREP + 255)/256, 256>>>(x, W_in, W_out, W_dt, W_x);

    gemm_f16x2<<<dim3(N_XZ/128, M_ROWS/128), 256, F2_SMEM>>>(
        xh, xl, wi16, xz, M_ROWS, N_XZ, DM);
    conv_silu_k<<<(M_ROWS*DI + 255)/256, 256>>>(W_conv);
    gemm_f16x2<<<dim3(N_COMB/128, M_ROWS/128), 256, F2_SMEM>>>(
        xch, xcl, wc16, dx, M_ROWS, N_COMB, DI);
    scan_a<<<dim3(DI/128, CCH, BATCH), 128>>>(A_log, b_dt);
    scan_b<<<dim3(DI/128, BATCH), 128>>>();
    scan_c<<<dim3(DI/128, CCH, BATCH), 128>>>(A_log, Dp, b_dt);
    gemm_fp16<<<dim3(DM/128, M_ROWS/64), 256, T3_SMEM>>>(
        y16, wo16, out, M_ROWS, DM, DI);
}